// round 10
// baseline (speedup 1.0000x reference)
#include <cuda_runtime.h>
#include <cstdint>

#define BB 64
#define SS 512
#define HH 1024
#define TT 17
#define NEG_INF (-3.402823466e+38f)
#define FULLM 0xffffffffu

#define FMA2(acc, a, w) \
    asm("fma.rn.f32x2 %0, %1, %2, %0;" : "+l"(acc) : "l"(a), "l"(w))
#define ADDF2(out, a, b) \
    asm("add.rn.f32x2 %0, %1, %2;" : "=l"(out) : "l"(a), "l"(b))
#define DUP2(out, w) \
    asm("mov.b64 %0, {%1, %1};" : "=l"(out) : "f"(w))
#define UNPACK2(lo, hi, in) \
    asm("mov.b64 {%0, %1}, %2;" : "=f"(lo), "=f"(hi) : "l"(in))

#define RPW   4
#define DEPTH 8
#define WTS   18
#define SHS   20

// cross-CTA producer->consumer flags; zero-init at load, reset by consumers
// each run so graph replays start clean.
__device__ int g_flags[1024];

// Fused kernel. Blocks 0..63: viterbi role (one batch each, wave-1 resident).
// Blocks 64..1087: GEMM role, s-major production order + flag signal.
__global__ __launch_bounds__(256)
void crf_fused_kernel(const float* __restrict__ x,
                      const float* __restrict__ W,
                      const float* __restrict__ bvec,
                      const float* __restrict__ trans,
                      const float* __restrict__ start_trans,
                      const float* __restrict__ end_trans,
                      const int*   __restrict__ nwords,
                      float* __restrict__ out_tags,
                      float* __restrict__ feats)
{
    extern __shared__ float sm[];
    const int tid  = threadIdx.x;
    const int lane = tid & 31;
    const int wid  = tid >> 5;

    if (blockIdx.x >= BB) {
        // ================= GEMM role (R7 body, s-major row mapping) ========
        const int g    = blockIdx.x - BB;
        const int bb   = g & 63;        // batch
        const int sblk = g >> 6;        // 32-row s-block within batch
        float* wT      = sm;                    // [1024][18]
        float* bias_sh = sm + HH * WTS;
        float* out_sh  = bias_sh + 20;

        if (tid < TT) bias_sh[tid] = bvec[tid];
        for (int i = tid; i < TT * HH; i += 256) {
            int t = i >> 10, k = i & 1023;
            wT[k * WTS + t] = W[i];
        }
        for (int k = tid; k < HH; k += 256) wT[k * WTS + TT] = 0.0f;
        __syncthreads();

        const size_t rowBase = (size_t)bb * SS + (size_t)sblk * 32
                             + (size_t)wid * RPW;
        const float* xp = x + rowBase * HH + lane;

        unsigned long long acc[RPW][9];
#pragma unroll
        for (int r = 0; r < RPW; r++)
#pragma unroll
            for (int j = 0; j < 9; j++) acc[r][j] = 0ull;

        float buf[DEPTH][RPW];
#pragma unroll
        for (int c = 0; c < DEPTH; c++)
#pragma unroll
            for (int r = 0; r < RPW; r++)
                buf[c][r] = __ldcs(xp + c * 32 + (size_t)r * HH);

#pragma unroll 8
        for (int c = 0; c < 32; c++) {
            const int slot = c & (DEPTH - 1);
            unsigned long long x2[RPW];
#pragma unroll
            for (int r = 0; r < RPW; r++) DUP2(x2[r], buf[slot][r]);
            if (c + DEPTH < 32) {
#pragma unroll
                for (int r = 0; r < RPW; r++)
                    buf[slot][r] = __ldcs(xp + (c + DEPTH) * 32 + (size_t)r * HH);
            }
            const float* wrow = &wT[(c * 32 + lane) * WTS];
#pragma unroll
            for (int j = 0; j < 9; j++) {
                unsigned long long w2 = *(const unsigned long long*)(wrow + 2 * j);
#pragma unroll
                for (int r = 0; r < RPW; r++) FMA2(acc[r][j], x2[r], w2);
            }
        }
        __syncthreads();   // wT dead -> reduction scratch

        unsigned long long* red = (unsigned long long*)wT;
        unsigned long long* myred = red + (size_t)wid * 36 * 32;
#pragma unroll
        for (int r = 0; r < RPW; r++)
#pragma unroll
            for (int j = 0; j < 9; j++)
                myred[(r * 9 + j) * 32 + lane] = acc[r][j];
        __syncthreads();

        for (int o = lane; o < 36; o += 32) {
            unsigned long long sum = 0ull;
#pragma unroll
            for (int jj = 0; jj < 32; jj++) {
                int l = (jj + lane) & 31;
                unsigned long long v = myred[o * 32 + l];
                ADDF2(sum, sum, v);
            }
            float lo, hi;
            UNPACK2(lo, hi, sum);
            int r = o / 9, j = o - 9 * r;
            int row = wid * RPW + r;
            out_sh[row * TT + 2 * j] = lo + bias_sh[2 * j];
            if (j < 8) out_sh[row * TT + 2 * j + 1] = hi + bias_sh[2 * j + 1];
        }
        __syncthreads();

        float4* dst = (float4*)(feats
                     + ((size_t)bb * SS + (size_t)sblk * 32) * TT);
        const float4* s4 = (const float4*)out_sh;
        for (int i = tid; i < 136; i += 256) dst[i] = s4[i];

        // signal block ready (release)
        __threadfence();
        __syncthreads();
        if (tid == 0) atomicExch(&g_flags[g], 1);
        return;
    }

    // ================= Viterbi role (R6 body + streamed block copy) ========
    float* feats_sh = sm;                                  // SS*TT+20 floats
    float* s_hist   = sm + (SS * TT + 20);                 // SS*SHS floats
    float* s_fin    = s_hist + SS * SHS;                   // 32 floats
    unsigned char* bp_sh = (unsigned char*)(s_fin + 32);   // 8704 B
    unsigned char* Csh   = bp_sh + SS * TT;                // 512 B
    int* ready = (int*)(Csh + 512);                        // 16 ints

    const int b = blockIdx.x;
    const int n = nwords[b];
    const int lanec = (lane < TT) ? lane : 0;

    if (tid < 16) ready[tid] = 0;
    if (tid < 20) feats_sh[SS * TT + tid] = 0.0f;          // prefetch pad
    float tc[TT];
#pragma unroll
    for (int i = 0; i < TT; i++)
        tc[i] = (lane < TT) ? trans[i * TT + lane] : NEG_INF;
    __syncthreads();

#define WAITBLK(kk) { while (((volatile int*)ready)[kk] == 0) {} \
                      __threadfence_block(); }

    if (wid == 0) {
        // ---- phase 1: serial value recurrence, consuming streamed blocks --
        WAITBLK(0);
        float s = (lane < TT) ? (start_trans[lane] + feats_sh[lane]) : NEG_INF;
        if (lane < TT) s_hist[lane] = s;
        __syncwarp();
        float fnext = feats_sh[TT + lanec];
        for (int t = 1; t < n; t++) {
            if ((t & 31) == 31) {
                int nb = (t >> 5) + 1;
                if (nb < 16) WAITBLK(nb);
            }
            const float* sp = &s_hist[(t - 1) * SHS];
            float4 q0 = *(const float4*)(sp + 0);
            float4 q1 = *(const float4*)(sp + 4);
            float4 q2 = *(const float4*)(sp + 8);
            float4 q3 = *(const float4*)(sp + 12);
            float  q4 = sp[16];
            float v0, v1, v2, v3, v4, v5, v6, v7;
            v0 = fmaxf(q0.x + tc[0],  q0.y + tc[1]);
            v1 = fmaxf(q0.z + tc[2],  q0.w + tc[3]);
            v2 = fmaxf(q1.x + tc[4],  q1.y + tc[5]);
            v3 = fmaxf(q1.z + tc[6],  q1.w + tc[7]);
            v4 = fmaxf(q2.x + tc[8],  q2.y + tc[9]);
            v5 = fmaxf(q2.z + tc[10], q2.w + tc[11]);
            v6 = fmaxf(q3.x + tc[12], q3.y + tc[13]);
            v7 = fmaxf(q3.z + tc[14], q3.w + tc[15]);
            v0 = fmaxf(v0, v1); v2 = fmaxf(v2, v3);
            v4 = fmaxf(v4, v5); v6 = fmaxf(v6, v7);
            v0 = fmaxf(v0, v2); v4 = fmaxf(v4, v6);
            v0 = fmaxf(v0, v4);
            v0 = fmaxf(v0, q4 + tc[16]);
            float f = fnext;
            fnext = feats_sh[(t + 1) * TT + lanec];   // padded: safe at t=511
            s = v0 + f;
            if (lane < TT) s_hist[t * SHS + lane] = s;
            __syncwarp();
        }
        s_fin[lane] = (lane < TT) ? (s + end_trans[lane]) : NEG_INF;
    } else {
        // ---- copier warps 1..7: stream feats blocks gmem -> smem ----
        for (int k = wid - 1; k < 16; k += 7) {
            const int g = k * 64 + b;
            while (atomicAdd(&g_flags[g], 0) == 0) {}
            __threadfence();                           // acquire
            const float4* src = (const float4*)(feats
                               + ((size_t)b * SS + (size_t)k * 32) * TT);
            float4* dstf = (float4*)(feats_sh + k * 32 * TT);
            for (int i = lane; i < 136; i += 32) dstf[i] = src[i];
            atomicExch(&g_flags[g], 0);                // reset for next replay
            __threadfence_block();                     // release (all lanes)
            __syncwarp();
            if (lane == 0) ((volatile int*)ready)[k] = 1;
        }
    }
    __syncthreads();

    // ---- phase 2: backpointers + composed survivor maps (parallel chunks) --
    for (int c = wid; c < 16; c += 8) {
        const int t0 = 32 * c + 1;
        const int t1 = (c == 15) ? (SS - 1) : (32 * (c + 1));
        int M = lane;
        for (int t = t0; t <= t1; t++) {
            if (t < n) {
                const float* sp = &s_hist[(t - 1) * SHS];
                float4 q0 = *(const float4*)(sp + 0);
                float4 q1 = *(const float4*)(sp + 4);
                float4 q2 = *(const float4*)(sp + 8);
                float4 q3 = *(const float4*)(sp + 12);
                float  q4 = sp[16];
                float v[TT];
                v[0]  = q0.x + tc[0];  v[1]  = q0.y + tc[1];
                v[2]  = q0.z + tc[2];  v[3]  = q0.w + tc[3];
                v[4]  = q1.x + tc[4];  v[5]  = q1.y + tc[5];
                v[6]  = q1.z + tc[6];  v[7]  = q1.w + tc[7];
                v[8]  = q2.x + tc[8];  v[9]  = q2.y + tc[9];
                v[10] = q2.z + tc[10]; v[11] = q2.w + tc[11];
                v[12] = q3.x + tc[12]; v[13] = q3.y + tc[13];
                v[14] = q3.z + tc[14]; v[15] = q3.w + tc[15];
                v[16] = q4   + tc[16];
                float m01 = fmaxf(v[0], v[1]),   m23 = fmaxf(v[2], v[3]);
                float m45 = fmaxf(v[4], v[5]),   m67 = fmaxf(v[6], v[7]);
                float m89 = fmaxf(v[8], v[9]),   mab = fmaxf(v[10], v[11]);
                float mcd = fmaxf(v[12], v[13]), mef = fmaxf(v[14], v[15]);
                float mA = fmaxf(fmaxf(m01, m23), fmaxf(m45, m67));
                float mB = fmaxf(fmaxf(m89, mab), fmaxf(mcd, mef));
                float m  = fmaxf(fmaxf(mA, mB), v[16]);
                unsigned g0 = ((v[0] == m) ? 1u : 0u)   | ((v[1] == m) ? 2u : 0u)
                            | ((v[2] == m) ? 4u : 0u)   | ((v[3] == m) ? 8u : 0u);
                unsigned g1 = ((v[4] == m) ? 16u : 0u)  | ((v[5] == m) ? 32u : 0u)
                            | ((v[6] == m) ? 64u : 0u)  | ((v[7] == m) ? 128u : 0u);
                unsigned g2 = ((v[8] == m) ? 256u : 0u)   | ((v[9] == m) ? 512u : 0u)
                            | ((v[10] == m) ? 1024u : 0u) | ((v[11] == m) ? 2048u : 0u);
                unsigned g3 = ((v[12] == m) ? 4096u : 0u) | ((v[13] == m) ? 8192u : 0u)
                            | ((v[14] == m) ? 16384u : 0u)| ((v[15] == m) ? 32768u : 0u)
                            | ((v[16] == m) ? 65536u : 0u);
                int bp = __ffs((g0 | g1) | (g2 | g3)) - 1;
                if (lane < TT) bp_sh[t * TT + lane] = (unsigned char)bp;
                M = __shfl_sync(FULLM, M, bp);
            }
        }
        Csh[c * 32 + lane] = (unsigned char)M;
    }
    __syncthreads();

    // ---- phase 3: final argmax, boundary chaining, parallel backtrack ----
    if (wid == 0) {
        float v = s_fin[lane];
        int ix = (lane < TT) ? lane : 99;
#pragma unroll
        for (int off = 16; off; off >>= 1) {
            float ov = __shfl_xor_sync(FULLM, v, off);
            int   oi = __shfl_xor_sync(FULLM, ix, off);
            if (ov > v || (ov == v && oi < ix)) { v = ov; ix = oi; }
        }
        const int last_tag = ix;

        int startTag = last_tag;            // lane 15: tag @ t = 511
        int cur = last_tag;
        for (int c = 15; c >= 1; c--) {
            cur = (int)Csh[c * 32 + cur];   // tag @ t = 32c
            if (lane == c - 1) startTag = cur;
        }
        __syncwarp();

        float* outT = out_tags + (size_t)b * SS;
        if (lane < 16) {
            int tag = startTag;
            const int tEnd = 32 * lane;
            const int tStart = (lane == 15) ? (SS - 1) : (32 * (lane + 1));
            for (int t = tStart; t > tEnd; t--) {
                if (t < n) {
                    outT[t] = (float)tag;
                    tag = (int)bp_sh[t * TT + tag];
                } else {
                    outT[t] = 0.0f;
                }
            }
            if (lane == 0) outT[0] = (float)tag;   // n >= 1: never masked
        }
    }
}

// ---------------------------------------------------------------------------
extern "C" void kernel_launch(void* const* d_in, const int* in_sizes, int n_in,
                              void* d_out, int out_size)
{
    const float* x     = (const float*)d_in[0];
    const float* W     = (const float*)d_in[1];
    const float* bvec  = (const float*)d_in[2];
    const float* trans = (const float*)d_in[3];
    const float* st    = (const float*)d_in[4];
    const float* en    = (const float*)d_in[5];
    const int*   nw    = (const int*)d_in[6];

    float* out   = (float*)d_out;
    float* tags  = out;                     // (B,S)   = 32768 floats
    float* feats = out + BB * SS;           // (B,S,T) = 557056 floats

    // max(GEMM 75984B, viterbi 85264B) + slack
    const int smBytes = 85504;
    cudaFuncSetAttribute(crf_fused_kernel,
                         cudaFuncAttributeMaxDynamicSharedMemorySize, smBytes);

    crf_fused_kernel<<<BB + 1024, 256, smBytes>>>(x, W, bvec, trans, st, en,
                                                  nw, tags, feats);
}